// round 1
// baseline (speedup 1.0000x reference)
#include <cuda_runtime.h>
#include <cuda_bf16.h>
#include <math.h>
#include <stdint.h>

// Problem constants (fixed by setup_inputs)
#define BATCH   512
#define TTEXT   64
#define EDIM    50
#define HDIM    32
#define NTL     32768
#define TTL     32
#define DNORM   49
#define FC_IN   305   // 64 + 49 + 64 + 64 + 64
#define HID     32

// -------- device scratch (no allocations allowed) --------
__device__ float g_hn[BATCH * 64];     // text biRNN final hidden [B, 2H]
__device__ float g_h2[NTL * 64];       // timeline biRNN final hidden [N, 2H]
__device__ float g_mean[BATCH * 64];
__device__ float g_min[BATCH * 64];
__device__ float g_max[BATCH * 64];

// ============================================================================
// Bidirectional Elman RNN, final hidden only.
// One warp per (sequence, direction). Lane l owns h[l].
// Weights per lane in registers; x_t / h_t broadcast via per-warp smem
// (double-buffered -> single __syncwarp per step). x(t+1) prefetched.
// ============================================================================
__global__ void __launch_bounds__(256) rnn_kernel(
    const float* __restrict__ X, int T, int Nseq, int which,
    const float* __restrict__ Wif, const float* __restrict__ Whf,
    const float* __restrict__ bif, const float* __restrict__ bhf,
    const float* __restrict__ Wib, const float* __restrict__ Whb,
    const float* __restrict__ bib, const float* __restrict__ bhb)
{
    __shared__ float sX[8][2][EDIM + 2];
    __shared__ float sH[8][2][HDIM];

    const int tid  = threadIdx.x;
    const int w    = tid >> 5;
    const int lane = tid & 31;
    const int gw   = blockIdx.x * 8 + w;
    const int n    = gw >> 1;
    const int d    = gw & 1;
    if (n >= Nseq) return;

    const float* Wi = d ? Wib : Wif;
    const float* Wh = d ? Whb : Whf;
    const float bias = d ? (bib[lane] + bhb[lane]) : (bif[lane] + bhf[lane]);

    // per-lane weight rows -> registers
    float wih[EDIM];
    float whh[HDIM];
#pragma unroll
    for (int j = 0; j < EDIM; ++j) wih[j] = Wi[lane * EDIM + j];
#pragma unroll
    for (int j = 0; j < HDIM; ++j) whh[j] = Wh[lane * HDIM + j];

    const float* xseq = X + (size_t)n * T * EDIM;

    // stage t=0
    {
        const int tt0 = d ? (T - 1) : 0;
        sH[w][0][lane] = 0.f;
        sX[w][0][lane] = xseq[tt0 * EDIM + lane];
        if (lane < EDIM - 32) sX[w][0][32 + lane] = xseq[tt0 * EDIM + 32 + lane];
    }
    __syncwarp();

    float hlast = 0.f;
    for (int t = 0; t < T; ++t) {
        const int cur = t & 1;
        const int nxt = cur ^ 1;

        // prefetch x(t+1) while computing
        float nx0 = 0.f, nx1 = 0.f;
        if (t + 1 < T) {
            const int tt = d ? (T - 2 - t) : (t + 1);
            nx0 = xseq[tt * EDIM + lane];
            if (lane < EDIM - 32) nx1 = xseq[tt * EDIM + 32 + lane];
        }

        const float* xs = sX[w][cur];
        const float* hs = sH[w][cur];
        float a0 = bias, a1 = 0.f;
#pragma unroll
        for (int j = 0; j < EDIM; j += 2) {
            a0 += xs[j]     * wih[j];
            a1 += xs[j + 1] * wih[j + 1];
        }
#pragma unroll
        for (int j = 0; j < HDIM; j += 2) {
            a0 += hs[j]     * whh[j];
            a1 += hs[j + 1] * whh[j + 1];
        }
        const float hnew = tanhf(a0 + a1);
        hlast = hnew;

        sH[w][nxt][lane] = hnew;
        sX[w][nxt][lane] = nx0;
        if (lane < EDIM - 32) sX[w][nxt][32 + lane] = nx1;
        __syncwarp();
    }

    float* Hout = which ? g_h2 : g_hn;
    Hout[(size_t)n * 64 + d * 32 + lane] = hlast;
}

// ============================================================================
// Ragged segment mean/min/max over g_h2 rows. One block (64 threads) per
// batch element; thread = column. Offsets derived from timeline_elements.
// ============================================================================
__global__ void seg_kernel(const int* __restrict__ elems)
{
    const int b   = blockIdx.x;
    const int tid = threadIdx.x;   // 0..63
    __shared__ int sred[64];

    int partial = 0;
    for (int i = tid; i < b; i += 64) partial += elems[i];
    sred[tid] = partial;
    __syncthreads();
    for (int s = 32; s; s >>= 1) {
        if (tid < s) sred[tid] += sred[tid + s];
        __syncthreads();
    }
    const int off = sred[0];
    const int cnt = elems[b];

    float s = 0.f, mn = 3.402823466e38f, mx = -3.402823466e38f;
    const float* base = g_h2 + (size_t)off * 64 + tid;
    for (int r = 0; r < cnt; ++r) {
        const float v = base[(size_t)r * 64];
        s += v;
        mn = fminf(mn, v);
        mx = fmaxf(mx, v);
    }
    g_mean[b * 64 + tid] = s / (float)cnt;
    g_min[b * 64 + tid]  = mn;
    g_max[b * 64 + tid]  = mx;
}

// ============================================================================
// Head: concat [h_n | normal | mean | min | max] (305) -> fc1 tanh -> fc2
// sigmoid. One warp per batch row; lane = fc1 hidden unit.
// ============================================================================
__global__ void head_kernel(const float* __restrict__ normal,
                            const float* __restrict__ fc1w,
                            const float* __restrict__ fc1b,
                            const float* __restrict__ fc2w,
                            const float* __restrict__ fc2b,
                            float* __restrict__ out)
{
    const int b    = blockIdx.x;
    const int lane = threadIdx.x;
    __shared__ float xr[FC_IN];

    for (int i = lane; i < 64; i += 32) {
        xr[i]        = g_hn[b * 64 + i];
        xr[113 + i]  = g_mean[b * 64 + i];
        xr[177 + i]  = g_min[b * 64 + i];
        xr[241 + i]  = g_max[b * 64 + i];
    }
    for (int i = lane; i < DNORM; i += 32) xr[64 + i] = normal[b * DNORM + i];
    __syncwarp();

    float acc = fc1b[lane];
    const float* wrow = fc1w + lane * FC_IN;
    for (int k = 0; k < FC_IN; ++k) acc += xr[k] * wrow[k];
    float p = tanhf(acc) * fc2w[lane];
#pragma unroll
    for (int o = 16; o; o >>= 1) p += __shfl_xor_sync(0xffffffffu, p, o);
    if (lane == 0) {
        const float z = p + fc2b[0];
        out[b] = 1.f / (1.f + expf(-z));
    }
}

// ============================================================================
// kernel_launch
// ============================================================================
extern "C" void kernel_launch(void* const* d_in, const int* in_sizes, int n_in,
                              void* d_out, int out_size)
{
    const float* normal   = (const float*)d_in[0];
    const float* text     = (const float*)d_in[1];
    const float* timeline = (const float*)d_in[2];

    // Input-order detection: setup_inputs dict order has timeline_elements
    // (512 ints) at slot 3; reference-signature order has rnn1_wif (1600) there.
    const int* elems;
    int base;
    if (in_sizes[3] == BATCH) {          // dict order
        elems = (const int*)d_in[3];
        base = 4;
    } else {                              // signature order: elems is last
        elems = (const int*)d_in[n_in - 1];
        base = 3;
    }

    const float* r1[8];
    const float* r2[8];
    for (int i = 0; i < 8; ++i) r1[i] = (const float*)d_in[base + i];
    for (int i = 0; i < 8; ++i) r2[i] = (const float*)d_in[base + 8 + i];
    const float* fc1w = (const float*)d_in[base + 16];
    const float* fc1b = (const float*)d_in[base + 17];
    const float* fc2w = (const float*)d_in[base + 18];
    const float* fc2b = (const float*)d_in[base + 19];

    // text biRNN: 512 seqs x 2 dirs = 1024 warps -> 128 blocks
    rnn_kernel<<<(BATCH * 2) / 8, 256>>>(
        text, TTEXT, BATCH, 0,
        r1[0], r1[1], r1[2], r1[3], r1[4], r1[5], r1[6], r1[7]);

    // timeline biRNN: 32768 x 2 = 65536 warps -> 8192 blocks
    rnn_kernel<<<(NTL * 2) / 8, 256>>>(
        timeline, TTL, NTL, 1,
        r2[0], r2[1], r2[2], r2[3], r2[4], r2[5], r2[6], r2[7]);

    seg_kernel<<<BATCH, 64>>>(elems);

    head_kernel<<<BATCH, 32>>>(normal, fc1w, fc1b, fc2w, fc2b, (float*)d_out);
}

// round 2
// speedup vs baseline: 1.2253x; 1.2253x over previous
#include <cuda_runtime.h>
#include <cuda_bf16.h>
#include <math.h>
#include <stdint.h>

// Problem constants (fixed by setup_inputs)
#define BATCH   512
#define TTEXT   64
#define EDIM    50
#define HDIM    32
#define NTL     32768
#define TTL     32
#define DNORM   49
#define FC_IN   305   // 64 + 49 + 64 + 64 + 64
#define GR      128   // rows per GEMM tile

typedef unsigned long long u64t;

// -------- device scratch (static; no runtime allocation) --------
__device__ float g_hn[BATCH * 64];            // text biRNN final hidden [B, 2H]
__device__ float g_h2[NTL * 64];              // timeline biRNN final hidden [N, 2H]
__device__ float g_mean[BATCH * 64];
__device__ float g_min[BATCH * 64];
__device__ float g_max[BATCH * 64];
__device__ float g_u2[NTL * TTL * 64];        // precomputed x@Wih^T + bias, timeline (268 MB)
__device__ float g_u1[BATCH * TTEXT * 64];    // same for text (8 MB)

// ---------------- packed f32x2 helpers ----------------
__device__ __forceinline__ u64t pk2(float a, float b) {
#if defined(__CUDA_ARCH__) && __CUDA_ARCH__ >= 1000
    u64t r; asm("mov.b64 %0,{%1,%2};" : "=l"(r) : "f"(a), "f"(b)); return r;
#else
    return ((u64t)__float_as_uint(b) << 32) | (u64t)__float_as_uint(a);
#endif
}
__device__ __forceinline__ void upk2(u64t v, float& a, float& b) {
#if defined(__CUDA_ARCH__) && __CUDA_ARCH__ >= 1000
    asm("mov.b64 {%0,%1},%2;" : "=f"(a), "=f"(b) : "l"(v));
#else
    a = __uint_as_float((unsigned)(v & 0xffffffffu));
    b = __uint_as_float((unsigned)(v >> 32));
#endif
}
__device__ __forceinline__ u64t fma2(u64t a, u64t b, u64t c) {
#if defined(__CUDA_ARCH__) && __CUDA_ARCH__ >= 1000
    u64t d; asm("fma.rn.f32x2 %0,%1,%2,%3;" : "=l"(d) : "l"(a), "l"(b), "l"(c)); return d;
#else
    float al, ah, bl, bh, cl, ch;
    upk2(a, al, ah); upk2(b, bl, bh); upk2(c, cl, ch);
    return pk2(fmaf(al, bl, cl), fmaf(ah, bh, ch));
#endif
}
__device__ __forceinline__ u64t add2(u64t a, u64t b) {
#if defined(__CUDA_ARCH__) && __CUDA_ARCH__ >= 1000
    u64t d; asm("add.rn.f32x2 %0,%1,%2;" : "=l"(d) : "l"(a), "l"(b)); return d;
#else
    float al, ah, bl, bh;
    upk2(a, al, ah); upk2(b, bl, bh);
    return pk2(al + bl, ah + bh);
#endif
}

// tanh(x) = 1 - 2/(e^{2x}+1) via MUFU ex2/rcp. rel err ~1e-6.
__device__ __forceinline__ float fast_tanh(float x) {
    float e, r;
    asm("ex2.approx.f32 %0,%1;" : "=f"(e) : "f"(x * 2.8853900817779268f));
    asm("rcp.approx.f32 %0,%1;" : "=f"(r) : "f"(e + 1.0f));
    return fmaf(-2.0f, r, 1.0f);
}
__device__ __forceinline__ float fast_sigmoid(float x) {
    float e, r;
    asm("ex2.approx.f32 %0,%1;" : "=f"(e) : "f"(-x * 1.4426950408889634f));
    asm("rcp.approx.f32 %0,%1;" : "=f"(r) : "f"(e + 1.0f));
    return r;
}

// ============================================================================
// GEMM: U[row, 0:32]  = X[row]·Wif^T + (bif+bhf)
//       U[row, 32:64] = X[row]·Wib^T + (bib+bhb)
// rows are (n,t) flattened; X rows contiguous (50 floats each).
// Lane owns output columns {lane, lane+32}; E packed in f32x2 pairs.
// ============================================================================
__global__ void __launch_bounds__(256) gemm_u_kernel(
    const float* __restrict__ X, float* __restrict__ U,
    const float* __restrict__ Wif, const float* __restrict__ bif, const float* __restrict__ bhf,
    const float* __restrict__ Wib, const float* __restrict__ bib, const float* __restrict__ bhb)
{
    __shared__ __align__(16) float4 sX4[GR * EDIM / 4];   // 25.6 KB

    const int tid  = threadIdx.x;
    const int w    = tid >> 5;
    const int lane = tid & 31;

    // per-lane weight rows as 64-bit E-pairs (registers)
    u64t wf[25], wb[25];
    const u64t* Wf2 = (const u64t*)(Wif + lane * EDIM);   // 200B rows -> 8B aligned
    const u64t* Wb2 = (const u64t*)(Wib + lane * EDIM);
#pragma unroll
    for (int j = 0; j < 25; ++j) { wf[j] = Wf2[j]; wb[j] = Wb2[j]; }
    const float bF = bif[lane] + bhf[lane];
    const float bB = bib[lane] + bhb[lane];

    const int row0 = blockIdx.x * GR;
    const float4* Xg = (const float4*)(X + (size_t)row0 * EDIM);
    for (int i = tid; i < GR * EDIM / 4; i += 256) sX4[i] = Xg[i];
    __syncthreads();

    const u64t* sx2 = (const u64t*)sX4;
    for (int r = w; r < GR; r += 8) {
        const u64t* xr = sx2 + r * 25;
        u64t aF = 0ull, aB = 0ull;   // {0.f,0.f}
#pragma unroll
        for (int j = 0; j < 25; ++j) {
            u64t xx = xr[j];                 // broadcast LDS.64
            aF = fma2(xx, wf[j], aF);
            aB = fma2(xx, wb[j], aB);
        }
        float f0, f1, b0, b1;
        upk2(aF, f0, f1); upk2(aB, b0, b1);
        float* uo = U + (size_t)(row0 + r) * 64;
        uo[lane]      = f0 + f1 + bF;
        uo[32 + lane] = b0 + b1 + bB;
    }
}

// ============================================================================
// Recurrence: h_t = tanh(u_t + h_{t-1}·Whh^T).
// One warp = (2 sequences, 1 direction), packed f32x2. Lane owns h[lane].
// ============================================================================
__global__ void __launch_bounds__(256) rec_kernel(
    const float* __restrict__ U, float* __restrict__ Hout, int T, int NseqPairs,
    const float* __restrict__ Whf, const float* __restrict__ Whb)
{
    __shared__ __align__(16) u64t sH[8][2][HDIM];

    const int tid  = threadIdx.x;
    const int w    = tid >> 5;
    const int lane = tid & 31;
    const int gw   = blockIdx.x * 8 + w;
    const int p    = gw >> 1;           // sequence pair
    const int d    = gw & 1;            // direction
    if (p >= NseqPairs) return;

    const float* Wh = d ? Whb : Whf;
    u64t wh[HDIM];
#pragma unroll
    for (int j = 0; j < HDIM; ++j) { float v = Wh[lane * HDIM + j]; wh[j] = pk2(v, v); }

    const int s0 = 2 * p, s1 = 2 * p + 1;
    const int off = d * 32 + lane;
    const int stride = d ? -64 : 64;
    const float* q0 = U + ((size_t)s0 * T + (d ? T - 1 : 0)) * 64 + off;
    const float* q1 = U + ((size_t)s1 * T + (d ? T - 1 : 0)) * 64 + off;

    sH[w][0][lane] = 0ull;
    float u0 = *q0, u1 = *q1;
    __syncwarp();

    u64t hl = 0ull;
    for (int i = 0; i < T; ++i) {
        const int cur = i & 1, nxt = cur ^ 1;

        float n0 = 0.f, n1 = 0.f;
        if (i + 1 < T) { n0 = q0[stride]; n1 = q1[stride]; }
        q0 += stride; q1 += stride;

        u64t acc  = pk2(u0, u1);
        u64t acc2 = 0ull;
        const u64t* hs = sH[w][cur];
#pragma unroll
        for (int j = 0; j < HDIM; j += 2) {
            acc  = fma2(hs[j],     wh[j],     acc);
            acc2 = fma2(hs[j + 1], wh[j + 1], acc2);
        }
        acc = add2(acc, acc2);
        float a0, a1; upk2(acc, a0, a1);
        hl = pk2(fast_tanh(a0), fast_tanh(a1));
        sH[w][nxt][lane] = hl;
        u0 = n0; u1 = n1;
        __syncwarp();
    }

    float h0, h1; upk2(hl, h0, h1);
    Hout[(size_t)s0 * 64 + off] = h0;
    Hout[(size_t)s1 * 64 + off] = h1;
}

// ============================================================================
// Ragged segment mean/min/max over g_h2. One block (64 threads) per batch row.
// ============================================================================
__global__ void seg_kernel(const int* __restrict__ elems)
{
    const int b   = blockIdx.x;
    const int tid = threadIdx.x;   // 0..63
    __shared__ int sred[64];

    int partial = 0;
    for (int i = tid; i < b; i += 64) partial += elems[i];
    sred[tid] = partial;
    __syncthreads();
    for (int s = 32; s; s >>= 1) {
        if (tid < s) sred[tid] += sred[tid + s];
        __syncthreads();
    }
    const int off = sred[0];
    const int cnt = elems[b];

    float s = 0.f, mn = 3.402823466e38f, mx = -3.402823466e38f;
    const float* base = g_h2 + (size_t)off * 64 + tid;
    int r = 0;
    for (; r + 4 <= cnt; r += 4) {
        float v0 = base[(size_t)(r + 0) * 64];
        float v1 = base[(size_t)(r + 1) * 64];
        float v2 = base[(size_t)(r + 2) * 64];
        float v3 = base[(size_t)(r + 3) * 64];
        s += (v0 + v1) + (v2 + v3);
        mn = fminf(mn, fminf(fminf(v0, v1), fminf(v2, v3)));
        mx = fmaxf(mx, fmaxf(fmaxf(v0, v1), fmaxf(v2, v3)));
    }
    for (; r < cnt; ++r) {
        float v = base[(size_t)r * 64];
        s += v; mn = fminf(mn, v); mx = fmaxf(mx, v);
    }
    g_mean[b * 64 + tid] = s / (float)cnt;
    g_min[b * 64 + tid]  = mn;
    g_max[b * 64 + tid]  = mx;
}

// ============================================================================
// Head: concat(305) -> fc1 tanh -> fc2 sigmoid. 128 threads per batch row;
// 4 warps split the k-dimension, smem-reduce, warp 0 finishes.
// ============================================================================
__global__ void __launch_bounds__(128) head_kernel(
    const float* __restrict__ normal,
    const float* __restrict__ fc1w, const float* __restrict__ fc1b,
    const float* __restrict__ fc2w, const float* __restrict__ fc2b,
    float* __restrict__ out)
{
    const int b    = blockIdx.x;
    const int tid  = threadIdx.x;
    const int wq   = tid >> 5;
    const int lane = tid & 31;
    __shared__ float xr[FC_IN + 3];
    __shared__ float part[4][32];

    if (tid < 64) {
        xr[tid]       = g_hn[b * 64 + tid];
        xr[113 + tid] = g_mean[b * 64 + tid];
        xr[177 + tid] = g_min[b * 64 + tid];
        xr[241 + tid] = g_max[b * 64 + tid];
    }
    for (int i = tid; i < DNORM; i += 128) xr[64 + i] = normal[b * DNORM + i];
    __syncthreads();

    const int k0 = wq * 76;
    const int k1 = (wq == 3) ? FC_IN : k0 + 76;
    const float* wrow = fc1w + lane * FC_IN;
    float a0 = 0.f, a1 = 0.f, a2 = 0.f, a3 = 0.f;
    int k = k0;
    for (; k + 4 <= k1; k += 4) {
        a0 += xr[k]     * wrow[k];
        a1 += xr[k + 1] * wrow[k + 1];
        a2 += xr[k + 2] * wrow[k + 2];
        a3 += xr[k + 3] * wrow[k + 3];
    }
    for (; k < k1; ++k) a0 += xr[k] * wrow[k];
    part[wq][lane] = (a0 + a1) + (a2 + a3);
    __syncthreads();

    if (wq == 0) {
        float acc = fc1b[lane] + part[0][lane] + part[1][lane] + part[2][lane] + part[3][lane];
        float pv = fast_tanh(acc) * fc2w[lane];
#pragma unroll
        for (int o = 16; o; o >>= 1) pv += __shfl_xor_sync(0xffffffffu, pv, o);
        if (lane == 0) out[b] = fast_sigmoid(pv + fc2b[0]);
    }
}

// ============================================================================
// kernel_launch
// ============================================================================
extern "C" void kernel_launch(void* const* d_in, const int* in_sizes, int n_in,
                              void* d_out, int out_size)
{
    const float* normal   = (const float*)d_in[0];
    const float* text     = (const float*)d_in[1];
    const float* timeline = (const float*)d_in[2];

    // Input-order detection: dict order puts timeline_elements (512 ints) at
    // slot 3; signature order puts it last.
    const int* elems;
    int base;
    if (in_sizes[3] == BATCH) { elems = (const int*)d_in[3]; base = 4; }
    else                      { elems = (const int*)d_in[n_in - 1]; base = 3; }

    const float* r1[8];
    const float* r2[8];
    for (int i = 0; i < 8; ++i) r1[i] = (const float*)d_in[base + i];
    for (int i = 0; i < 8; ++i) r2[i] = (const float*)d_in[base + 8 + i];
    const float* fc1w = (const float*)d_in[base + 16];
    const float* fc1b = (const float*)d_in[base + 17];
    const float* fc2w = (const float*)d_in[base + 18];
    const float* fc2b = (const float*)d_in[base + 19];
    // order per dir: wi, wh, bi, bh ; fwd then bwd
    // r[0]=wif r[1]=whf r[2]=bif r[3]=bhf r[4]=wib r[5]=whb r[6]=bib r[7]=bhb

    float* u1; cudaGetSymbolAddress((void**)&u1, g_u1);
    float* u2; cudaGetSymbolAddress((void**)&u2, g_u2);
    float* hn; cudaGetSymbolAddress((void**)&hn, g_hn);
    float* h2; cudaGetSymbolAddress((void**)&h2, g_h2);

    // text: 32768 rows
    gemm_u_kernel<<<(BATCH * TTEXT) / GR, 256>>>(
        text, u1, r1[0], r1[2], r1[3], r1[4], r1[6], r1[7]);
    // timeline: 1,048,576 rows
    gemm_u_kernel<<<(NTL * TTL) / GR, 256>>>(
        timeline, u2, r2[0], r2[2], r2[3], r2[4], r2[6], r2[7]);

    // recurrences: warp = (2 seqs, 1 dir); 8 warps/block
    rec_kernel<<<(BATCH / 2 * 2) / 8, 256>>>(u1, hn, TTEXT, BATCH / 2, r1[1], r1[5]);
    rec_kernel<<<(NTL / 2 * 2) / 8, 256>>>(u2, h2, TTL, NTL / 2, r2[1], r2[5]);

    seg_kernel<<<BATCH, 64>>>(elems);

    head_kernel<<<BATCH, 128>>>(normal, fc1w, fc1b, fc2w, fc2b, (float*)d_out);
}

// round 3
// speedup vs baseline: 1.3066x; 1.0663x over previous
#include <cuda_runtime.h>
#include <cuda_bf16.h>
#include <math.h>
#include <stdint.h>

// Problem constants (fixed by setup_inputs)
#define BATCH   512
#define TTEXT   64
#define EDIM    50
#define HDIM    32
#define NTL     32768
#define TTL     32
#define DNORM   49
#define FC_IN   305   // 64 + 49 + 64 + 64 + 64
#define GR      128   // rows per GEMM tile
#define SROW    28    // padded smem row pitch in u64 units (224B, 16B-aligned)

typedef unsigned long long u64t;

// -------- device scratch (static; no runtime allocation) --------
__device__ float g_hn[BATCH * 64];            // text biRNN final hidden [B, 2H]
__device__ float g_h2[NTL * 64];              // timeline biRNN final hidden [N, 2H]
__device__ float g_mean[BATCH * 64];
__device__ float g_min[BATCH * 64];
__device__ float g_max[BATCH * 64];
__device__ float g_u2[NTL * TTL * 64];        // x@Wih^T + bias, timeline (268 MB)
__device__ float g_u1[BATCH * TTEXT * 64];    // same for text (8 MB)

// ---------------- packed f32x2 helpers ----------------
__device__ __forceinline__ u64t pk2(float a, float b) {
    u64t r; asm("mov.b64 %0,{%1,%2};" : "=l"(r) : "f"(a), "f"(b)); return r;
}
__device__ __forceinline__ void upk2(u64t v, float& a, float& b) {
    asm("mov.b64 {%0,%1},%2;" : "=f"(a), "=f"(b) : "l"(v));
}
__device__ __forceinline__ u64t fma2(u64t a, u64t b, u64t c) {
    u64t d; asm("fma.rn.f32x2 %0,%1,%2,%3;" : "=l"(d) : "l"(a), "l"(b), "l"(c)); return d;
}
__device__ __forceinline__ u64t add2(u64t a, u64t b) {
    u64t d; asm("add.rn.f32x2 %0,%1,%2;" : "=l"(d) : "l"(a), "l"(b)); return d;
}

// tanh(x) = 1 - 2/(e^{2x}+1) via MUFU ex2/rcp.
__device__ __forceinline__ float fast_tanh(float x) {
    float e, r;
    asm("ex2.approx.f32 %0,%1;" : "=f"(e) : "f"(x * 2.8853900817779268f));
    asm("rcp.approx.f32 %0,%1;" : "=f"(r) : "f"(e + 1.0f));
    return fmaf(-2.0f, r, 1.0f);
}
__device__ __forceinline__ float fast_sigmoid(float x) {
    float e, r;
    asm("ex2.approx.f32 %0,%1;" : "=f"(e) : "f"(-x * 1.4426950408889634f));
    asm("rcp.approx.f32 %0,%1;" : "=f"(r) : "f"(e + 1.0f));
    return r;
}

// ============================================================================
// GEMM: U[row, 0:32] = X[row]·Wif^T + (bif+bhf); U[row,32:64] = X·Wib^T + bB.
// Merged launch: blocks [0, tlBlocks) -> timeline, rest -> text.
// x staged in smem with 224B row pitch -> LDS.128 inner loop.
// ============================================================================
__global__ void __launch_bounds__(256) gemm_u_kernel(
    int tlBlocks,
    const float* __restrict__ Xl, float* __restrict__ Ul,
    const float* __restrict__ l_Wif, const float* __restrict__ l_bif, const float* __restrict__ l_bhf,
    const float* __restrict__ l_Wib, const float* __restrict__ l_bib, const float* __restrict__ l_bhb,
    const float* __restrict__ Xt, float* __restrict__ Ut,
    const float* __restrict__ t_Wif, const float* __restrict__ t_bif, const float* __restrict__ t_bhf,
    const float* __restrict__ t_Wib, const float* __restrict__ t_bib, const float* __restrict__ t_bhb)
{
    __shared__ __align__(16) u64t sX[GR * SROW];   // 28.7 KB

    const int tid  = threadIdx.x;
    const int w    = tid >> 5;
    const int lane = tid & 31;

    const bool isTL = (blockIdx.x < tlBlocks);
    const int  blk  = isTL ? blockIdx.x : (blockIdx.x - tlBlocks);
    const float* X  = isTL ? Xl : Xt;
    float*       U  = isTL ? Ul : Ut;
    const float* Wif = isTL ? l_Wif : t_Wif;
    const float* Wib = isTL ? l_Wib : t_Wib;

    // per-lane weight rows as 64-bit E-pairs (registers)
    u64t wf[25], wb[25];
    {
        const u64t* Wf2 = (const u64t*)(Wif + lane * EDIM);
        const u64t* Wb2 = (const u64t*)(Wib + lane * EDIM);
#pragma unroll
        for (int j = 0; j < 25; ++j) { wf[j] = Wf2[j]; wb[j] = Wb2[j]; }
    }
    const float bF = isTL ? (l_bif[lane] + l_bhf[lane]) : (t_bif[lane] + t_bhf[lane]);
    const float bB = isTL ? (l_bib[lane] + l_bhb[lane]) : (t_bib[lane] + t_bhb[lane]);

    const int row0 = blk * GR;
    // stage X rows into padded smem (global contiguous float2 reads)
    {
        const u64t* Xg = (const u64t*)(X + (size_t)row0 * EDIM);
        for (int i = tid; i < GR * 25; i += 256) {
            sX[(i / 25) * SROW + (i % 25)] = Xg[i];
        }
    }
    __syncthreads();

    for (int r = w; r < GR; r += 8) {
        const u64t* xr = sX + r * SROW;
        const ulonglong2* x4 = (const ulonglong2*)xr;
        u64t aF = 0ull, aF2 = 0ull, aB = 0ull, aB2 = 0ull;
#pragma unroll
        for (int jp = 0; jp < 12; ++jp) {
            ulonglong2 xx = x4[jp];              // LDS.128: j-pairs 2jp, 2jp+1
            aF  = fma2(xx.x, wf[2 * jp],     aF);
            aF2 = fma2(xx.y, wf[2 * jp + 1], aF2);
            aB  = fma2(xx.x, wb[2 * jp],     aB);
            aB2 = fma2(xx.y, wb[2 * jp + 1], aB2);
        }
        {
            u64t xt = xr[24];                    // last j-pair
            aF = fma2(xt, wf[24], aF);
            aB = fma2(xt, wb[24], aB);
        }
        aF = add2(aF, aF2);
        aB = add2(aB, aB2);
        float f0, f1, b0, b1;
        upk2(aF, f0, f1); upk2(aB, b0, b1);
        float* uo = U + (size_t)(row0 + r) * 64;
        uo[lane]      = f0 + f1 + bF;
        uo[32 + lane] = b0 + b1 + bB;
    }
}

// ============================================================================
// Recurrence: h_t = tanh(u_t + h_{t-1}·Whh^T).
// One warp = (4 sequences, 1 direction). h in smem as [j][4 seqs] -> LDS.128
// feeds 4 sequences per instruction. 4 independent f32x2 accumulator chains.
// Merged launch: blocks [0, tlBlocks) -> timeline, rest -> text.
// ============================================================================
__global__ void __launch_bounds__(256) rec_kernel(
    int tlBlocks,
    const float* __restrict__ Ul, float* __restrict__ Hl, int Tl, int tlGroups,
    const float* __restrict__ l_Whf, const float* __restrict__ l_Whb,
    const float* __restrict__ Ut, float* __restrict__ Ht, int Tt,
    const float* __restrict__ t_Whf, const float* __restrict__ t_Whb)
{
    __shared__ __align__(16) ulonglong2 sH[8][2][HDIM];   // 8 KB

    const int tid  = threadIdx.x;
    const int w    = tid >> 5;
    const int lane = tid & 31;

    const bool isTL = (blockIdx.x < tlBlocks);
    const int  blk  = isTL ? blockIdx.x : (blockIdx.x - tlBlocks);
    const float* U  = isTL ? Ul : Ut;
    float*    Hout  = isTL ? Hl : Ht;
    const int T     = isTL ? Tl : Tt;

    const int gw = blk * 8 + w;
    const int g  = gw >> 1;          // group of 4 sequences
    const int d  = gw & 1;           // direction

    const float* Wh = isTL ? (d ? l_Whb : l_Whf) : (d ? t_Whb : t_Whf);
    u64t wh[HDIM];
#pragma unroll
    for (int j = 0; j < HDIM; ++j) { float v = Wh[lane * HDIM + j]; wh[j] = pk2(v, v); }

    const int s0     = 4 * g;
    const int off    = d * 32 + lane;
    const int stride = d ? -64 : 64;
    const int seqStride = T * 64;
    const float* q = U + ((size_t)s0 * T + (d ? T - 1 : 0)) * 64 + off;

    sH[w][0][lane] = make_ulonglong2(0ull, 0ull);
    float u0 = q[0], u1 = q[seqStride], u2 = q[2 * seqStride], u3 = q[3 * seqStride];
    __syncwarp();

    u64t hlA = 0ull, hlB = 0ull;
    for (int t = 0; t < T; ++t) {
        const int cur = t & 1, nxt = cur ^ 1;

        float n0 = 0.f, n1 = 0.f, n2 = 0.f, n3 = 0.f;
        if (t + 1 < T) {
            n0 = q[stride];
            n1 = q[stride + seqStride];
            n2 = q[stride + 2 * seqStride];
            n3 = q[stride + 3 * seqStride];
        }
        q += stride;

        u64t aA = pk2(u0, u1), aB = pk2(u2, u3);
        u64t aA2 = 0ull, aB2 = 0ull;
        const ulonglong2* hs = sH[w][cur];
#pragma unroll
        for (int j = 0; j < HDIM; j += 2) {
            ulonglong2 h0 = hs[j];       // {s0,s1 | s2,s3} at col j
            ulonglong2 h1 = hs[j + 1];
            aA  = fma2(h0.x, wh[j],     aA);
            aB  = fma2(h0.y, wh[j],     aB);
            aA2 = fma2(h1.x, wh[j + 1], aA2);
            aB2 = fma2(h1.y, wh[j + 1], aB2);
        }
        aA = add2(aA, aA2);
        aB = add2(aB, aB2);
        float a0, a1, a2, a3;
        upk2(aA, a0, a1); upk2(aB, a2, a3);
        hlA = pk2(fast_tanh(a0), fast_tanh(a1));
        hlB = pk2(fast_tanh(a2), fast_tanh(a3));
        sH[w][nxt][lane] = make_ulonglong2(hlA, hlB);
        u0 = n0; u1 = n1; u2 = n2; u3 = n3;
        __syncwarp();
    }

    float h0, h1, h2, h3;
    upk2(hlA, h0, h1); upk2(hlB, h2, h3);
    Hout[(size_t)(s0 + 0) * 64 + off] = h0;
    Hout[(size_t)(s0 + 1) * 64 + off] = h1;
    Hout[(size_t)(s0 + 2) * 64 + off] = h2;
    Hout[(size_t)(s0 + 3) * 64 + off] = h3;
}

// ============================================================================
// Ragged segment mean/min/max over g_h2. One block (64 threads) per batch row.
// ============================================================================
__global__ void seg_kernel(const int* __restrict__ elems)
{
    const int b   = blockIdx.x;
    const int tid = threadIdx.x;   // 0..63
    __shared__ int sred[64];

    int partial = 0;
    for (int i = tid; i < b; i += 64) partial += elems[i];
    sred[tid] = partial;
    __syncthreads();
    for (int s = 32; s; s >>= 1) {
        if (tid < s) sred[tid] += sred[tid + s];
        __syncthreads();
    }
    const int off = sred[0];
    const int cnt = elems[b];

    float s = 0.f, mn = 3.402823466e38f, mx = -3.402823466e38f;
    const float* base = g_h2 + (size_t)off * 64 + tid;
    int r = 0;
    for (; r + 4 <= cnt; r += 4) {
        float v0 = base[(size_t)(r + 0) * 64];
        float v1 = base[(size_t)(r + 1) * 64];
        float v2 = base[(size_t)(r + 2) * 64];
        float v3 = base[(size_t)(r + 3) * 64];
        s += (v0 + v1) + (v2 + v3);
        mn = fminf(mn, fminf(fminf(v0, v1), fminf(v2, v3)));
        mx = fmaxf(mx, fmaxf(fmaxf(v0, v1), fmaxf(v2, v3)));
    }
    for (; r < cnt; ++r) {
        float v = base[(size_t)r * 64];
        s += v; mn = fminf(mn, v); mx = fmaxf(mx, v);
    }
    g_mean[b * 64 + tid] = s / (float)cnt;
    g_min[b * 64 + tid]  = mn;
    g_max[b * 64 + tid]  = mx;
}

// ============================================================================
// Head: concat(305) -> fc1 tanh -> fc2 sigmoid. 128 threads per batch row.
// ============================================================================
__global__ void __launch_bounds__(128) head_kernel(
    const float* __restrict__ normal,
    const float* __restrict__ fc1w, const float* __restrict__ fc1b,
    const float* __restrict__ fc2w, const float* __restrict__ fc2b,
    float* __restrict__ out)
{
    const int b    = blockIdx.x;
    const int tid  = threadIdx.x;
    const int wq   = tid >> 5;
    const int lane = tid & 31;
    __shared__ float xr[FC_IN + 3];
    __shared__ float part[4][32];

    if (tid < 64) {
        xr[tid]       = g_hn[b * 64 + tid];
        xr[113 + tid] = g_mean[b * 64 + tid];
        xr[177 + tid] = g_min[b * 64 + tid];
        xr[241 + tid] = g_max[b * 64 + tid];
    }
    for (int i = tid; i < DNORM; i += 128) xr[64 + i] = normal[b * DNORM + i];
    __syncthreads();

    const int k0 = wq * 76;
    const int k1 = (wq == 3) ? FC_IN : k0 + 76;
    const float* wrow = fc1w + lane * FC_IN;
    float a0 = 0.f, a1 = 0.f, a2 = 0.f, a3 = 0.f;
    int k = k0;
    for (; k + 4 <= k1; k += 4) {
        a0 += xr[k]     * wrow[k];
        a1 += xr[k + 1] * wrow[k + 1];
        a2 += xr[k + 2] * wrow[k + 2];
        a3 += xr[k + 3] * wrow[k + 3];
    }
    for (; k < k1; ++k) a0 += xr[k] * wrow[k];
    part[wq][lane] = (a0 + a1) + (a2 + a3);
    __syncthreads();

    if (wq == 0) {
        float acc = fc1b[lane] + part[0][lane] + part[1][lane] + part[2][lane] + part[3][lane];
        float pv = fast_tanh(acc) * fc2w[lane];
#pragma unroll
        for (int o = 16; o; o >>= 1) pv += __shfl_xor_sync(0xffffffffu, pv, o);
        if (lane == 0) out[b] = fast_sigmoid(pv + fc2b[0]);
    }
}

// ============================================================================
// kernel_launch
// ============================================================================
extern "C" void kernel_launch(void* const* d_in, const int* in_sizes, int n_in,
                              void* d_out, int out_size)
{
    const float* normal   = (const float*)d_in[0];
    const float* text     = (const float*)d_in[1];
    const float* timeline = (const float*)d_in[2];

    const int* elems;
    int base;
    if (in_sizes[3] == BATCH) { elems = (const int*)d_in[3]; base = 4; }
    else                      { elems = (const int*)d_in[n_in - 1]; base = 3; }

    const float* r1[8];
    const float* r2[8];
    for (int i = 0; i < 8; ++i) r1[i] = (const float*)d_in[base + i];
    for (int i = 0; i < 8; ++i) r2[i] = (const float*)d_in[base + 8 + i];
    const float* fc1w = (const float*)d_in[base + 16];
    const float* fc1b = (const float*)d_in[base + 17];
    const float* fc2w = (const float*)d_in[base + 18];
    const float* fc2b = (const float*)d_in[base + 19];
    // per dir: wi, wh, bi, bh ; fwd then bwd

    float* u1; cudaGetSymbolAddress((void**)&u1, g_u1);
    float* u2; cudaGetSymbolAddress((void**)&u2, g_u2);
    float* hn; cudaGetSymbolAddress((void**)&hn, g_hn);
    float* h2; cudaGetSymbolAddress((void**)&h2, g_h2);

    // merged GEMM: timeline 8192 blocks + text 256 blocks
    const int tlG = (NTL * TTL) / GR;
    const int txG = (BATCH * TTEXT) / GR;
    gemm_u_kernel<<<tlG + txG, 256>>>(
        tlG,
        timeline, u2, r2[0], r2[2], r2[3], r2[4], r2[6], r2[7],
        text,     u1, r1[0], r1[2], r1[3], r1[4], r1[6], r1[7]);

    // merged recurrence: warp = (4 seqs, 1 dir)
    const int tlR = (NTL / 4 * 2) / 8;     // 2048 blocks
    const int txR = (BATCH / 4 * 2) / 8;   // 32 blocks
    rec_kernel<<<tlR + txR, 256>>>(
        tlR,
        u2, h2, TTL, NTL / 4, r2[1], r2[5],
        u1, hn, TTEXT,        r1[1], r1[5]);

    seg_kernel<<<BATCH, 64>>>(elems);

    head_kernel<<<BATCH, 128>>>(normal, fc1w, fc1b, fc2w, fc2b, (float*)d_out);
}

// round 4
// speedup vs baseline: 1.5455x; 1.1829x over previous
#include <cuda_runtime.h>
#include <cuda_bf16.h>
#include <math.h>
#include <stdint.h>

// Problem constants (fixed by setup_inputs)
#define BATCH   512
#define TTEXT   64
#define EDIM    50
#define HDIM    32
#define NTL     32768
#define TTL     32
#define DNORM   49
#define FC_IN   305   // 64 + 49 + 64 + 64 + 64

typedef unsigned long long u64t;

// -------- device scratch (static; no runtime allocation) --------
__device__ float g_hn[BATCH * 64];            // text biRNN final hidden [B, 2H]
__device__ float g_h2[NTL * 64];              // timeline biRNN final hidden [N, 2H]
__device__ float g_mean[BATCH * 64];
__device__ float g_min[BATCH * 64];
__device__ float g_max[BATCH * 64];

// ---------------- packed f32x2 helpers ----------------
__device__ __forceinline__ u64t pk2(float a, float b) {
    u64t r; asm("mov.b64 %0,{%1,%2};" : "=l"(r) : "f"(a), "f"(b)); return r;
}
__device__ __forceinline__ void upk2(u64t v, float& a, float& b) {
    asm("mov.b64 {%0,%1},%2;" : "=f"(a), "=f"(b) : "l"(v));
}
__device__ __forceinline__ u64t fma2(u64t a, u64t b, u64t c) {
    u64t d; asm("fma.rn.f32x2 %0,%1,%2,%3;" : "=l"(d) : "l"(a), "l"(b), "l"(c)); return d;
}
__device__ __forceinline__ u64t add2(u64t a, u64t b) {
    u64t d; asm("add.rn.f32x2 %0,%1,%2;" : "=l"(d) : "l"(a), "l"(b)); return d;
}

// tanh(x) = 1 - 2/(e^{2x}+1) via MUFU ex2/rcp.
__device__ __forceinline__ float fast_tanh(float x) {
    float e, r;
    asm("ex2.approx.f32 %0,%1;" : "=f"(e) : "f"(x * 2.8853900817779268f));
    asm("rcp.approx.f32 %0,%1;" : "=f"(r) : "f"(e + 1.0f));
    return fmaf(-2.0f, r, 1.0f);
}
__device__ __forceinline__ float fast_sigmoid(float x) {
    float e, r;
    asm("ex2.approx.f32 %0,%1;" : "=f"(e) : "f"(-x * 1.4426950408889634f));
    asm("rcp.approx.f32 %0,%1;" : "=f"(r) : "f"(e + 1.0f));
    return r;
}

// u-dot for one sequence from a staged smem row (25 u64 E-pairs, 16B aligned)
__device__ __forceinline__ float u_dot(const u64t* __restrict__ xrow,
                                       const u64t* __restrict__ wi)
{
    const ulonglong2* x2 = (const ulonglong2*)xrow;
    u64t c0 = 0ull, c1 = 0ull;
#pragma unroll
    for (int jp = 0; jp < 12; ++jp) {
        ulonglong2 xx = x2[jp];            // LDS.128 broadcast
        c0 = fma2(xx.x, wi[2 * jp],     c0);
        c1 = fma2(xx.y, wi[2 * jp + 1], c1);
    }
    c0 = fma2(xrow[24], wi[24], c0);
    c0 = add2(c0, c1);
    float f0, f1; upk2(c0, f0, f1);
    return f0 + f1;
}

// ============================================================================
// Fused biRNN: h_t = tanh(x_t·Wih^T + bias + h_{t-1}·Whh^T), final h only.
// One warp = (4 sequences, 1 direction). Wih + Whh in registers.
// Per-warp smem: double-buffered x tiles (broadcast LDS.128) + packed h.
// Pipeline per step: LDG x_{t+2} | compute u_{t+1} | rec step t | STS x_{t+2}.
// Merged launch: blocks [0, tlBlocks) -> timeline, rest -> text.
// ============================================================================
__global__ void __launch_bounds__(256, 1) fused_rnn_kernel(
    int tlBlocks,
    const float* __restrict__ Xl, float* __restrict__ Hl, int Tl,
    const float* __restrict__ l_Wif, const float* __restrict__ l_Whf,
    const float* __restrict__ l_bif, const float* __restrict__ l_bhf,
    const float* __restrict__ l_Wib, const float* __restrict__ l_Whb,
    const float* __restrict__ l_bib, const float* __restrict__ l_bhb,
    const float* __restrict__ Xt, float* __restrict__ Ht, int Tt,
    const float* __restrict__ t_Wif, const float* __restrict__ t_Whf,
    const float* __restrict__ t_bif, const float* __restrict__ t_bhf,
    const float* __restrict__ t_Wib, const float* __restrict__ t_Whb,
    const float* __restrict__ t_bib, const float* __restrict__ t_bhb)
{
    __shared__ __align__(16) u64t sX[8][2][4][26];        // 13.3 KB
    __shared__ __align__(16) ulonglong2 sH[8][2][HDIM];   // 8 KB

    const int tid  = threadIdx.x;
    const int w    = tid >> 5;
    const int lane = tid & 31;

    const bool isTL = (blockIdx.x < tlBlocks);
    const int  blk  = isTL ? blockIdx.x : (blockIdx.x - tlBlocks);
    const float* X  = isTL ? Xl : Xt;
    float*    Hout  = isTL ? Hl : Ht;
    const int T     = isTL ? Tl : Tt;

    const int gw = blk * 8 + w;
    const int g  = gw >> 1;          // group of 4 sequences
    const int d  = gw & 1;           // direction

    const float* Wi = isTL ? (d ? l_Wib : l_Wif) : (d ? t_Wib : t_Wif);
    const float* Wh = isTL ? (d ? l_Whb : l_Whf) : (d ? t_Whb : t_Whf);
    const float* bi = isTL ? (d ? l_bib : l_bif) : (d ? t_bib : t_bif);
    const float* bh = isTL ? (d ? l_bhb : l_bhf) : (d ? t_bhb : t_bhf);

    // per-lane weight rows -> registers
    u64t wi[25];
    {
        const u64t* Wi2 = (const u64t*)(Wi + lane * EDIM);
#pragma unroll
        for (int j = 0; j < 25; ++j) wi[j] = Wi2[j];
    }
    u64t wh[HDIM];
#pragma unroll
    for (int j = 0; j < HDIM; ++j) { float v = Wh[lane * HDIM + j]; wh[j] = pk2(v, v); }
    const float bias = bi[lane] + bh[lane];

    const int s0 = 4 * g;
    const long sgn = d ? -25 : 25;          // per-step stride in u64 units
    const long t0  = d ? (long)(T - 1) * 25 : 0;

    // staging constants: lane covers flat idx {lane, lane+32, lane+64, lane+96}
    // of the 4x25 u64 tile
    const u64t* XB = (const u64t*)X;
    const u64t* pf[4];
    u64t* sts[4][2];
    bool act[4];
#pragma unroll
    for (int k = 0; k < 4; ++k) {
        int idx = lane + 32 * k;
        act[k] = idx < 100;
        int s = idx / 25, j = idx % 25;
        if (!act[k]) { s = 0; j = 0; }
        pf[k] = XB + ((size_t)(s0 + s) * T) * 25 + t0 + j;
        sts[k][0] = &sX[w][0][s][j];
        sts[k][1] = &sX[w][1][s][j];
    }

    // prologue: stage x0 -> buf0, x1 -> buf1
#pragma unroll
    for (int k = 0; k < 4; ++k) {
        if (act[k]) { *sts[k][0] = *pf[k]; pf[k] += sgn; }
    }
    if (T > 1) {
#pragma unroll
        for (int k = 0; k < 4; ++k) {
            if (act[k]) { *sts[k][1] = *pf[k]; pf[k] += sgn; }
        }
    }
    sH[w][0][lane] = make_ulonglong2(0ull, 0ull);
    __syncwarp();

    // u for step 0
    u64t uc01, uc23;
    {
        float u0 = u_dot(sX[w][0][0], wi) + bias;
        float u1 = u_dot(sX[w][0][1], wi) + bias;
        float u2 = u_dot(sX[w][0][2], wi) + bias;
        float u3 = u_dot(sX[w][0][3], wi) + bias;
        uc01 = pk2(u0, u1); uc23 = pk2(u2, u3);
    }

    u64t hlA = 0ull, hlB = 0ull;
    for (int t = 0; t < T; ++t) {
        const int cur = t & 1, nxt = cur ^ 1;

        // 1. prefetch x_{t+2} into registers
        u64t r0 = 0, r1 = 0, r2 = 0, r3 = 0;
        const bool havePF = (t + 2 < T);
        if (havePF) {
            if (act[0]) { r0 = *pf[0]; pf[0] += sgn; }
            if (act[1]) { r1 = *pf[1]; pf[1] += sgn; }
            if (act[2]) { r2 = *pf[2]; pf[2] += sgn; }
            if (act[3]) { r3 = *pf[3]; pf[3] += sgn; }
        }

        // 2. compute u_{t+1} from buf[nxt] (independent of h -> fills bubbles)
        u64t un01 = uc01, un23 = uc23;
        if (t + 1 < T) {
            float u0 = u_dot(sX[w][nxt][0], wi) + bias;
            float u1 = u_dot(sX[w][nxt][1], wi) + bias;
            float u2 = u_dot(sX[w][nxt][2], wi) + bias;
            float u3 = u_dot(sX[w][nxt][3], wi) + bias;
            un01 = pk2(u0, u1); un23 = pk2(u2, u3);
        }

        // 3. recurrence for step t
        {
            u64t aA = uc01, aB = uc23, aA2 = 0ull, aB2 = 0ull;
            const ulonglong2* hs = sH[w][cur];
#pragma unroll
            for (int j = 0; j < HDIM; j += 2) {
                ulonglong2 h0 = hs[j];
                ulonglong2 h1 = hs[j + 1];
                aA  = fma2(h0.x, wh[j],     aA);
                aB  = fma2(h0.y, wh[j],     aB);
                aA2 = fma2(h1.x, wh[j + 1], aA2);
                aB2 = fma2(h1.y, wh[j + 1], aB2);
            }
            aA = add2(aA, aA2);
            aB = add2(aB, aB2);
            float a0, a1, a2, a3;
            upk2(aA, a0, a1); upk2(aB, a2, a3);
            hlA = pk2(fast_tanh(a0), fast_tanh(a1));
            hlB = pk2(fast_tanh(a2), fast_tanh(a3));
            sH[w][nxt][lane] = make_ulonglong2(hlA, hlB);
        }

        // 4. store x_{t+2} into buf[cur] (x_t there is dead)
        if (havePF) {
            if (act[0]) *sts[0][cur] = r0;
            if (act[1]) *sts[1][cur] = r1;
            if (act[2]) *sts[2][cur] = r2;
            if (act[3]) *sts[3][cur] = r3;
        }
        __syncwarp();
        uc01 = un01; uc23 = un23;
    }

    const int off = d * 32 + lane;
    float h0, h1, h2, h3;
    upk2(hlA, h0, h1); upk2(hlB, h2, h3);
    Hout[(size_t)(s0 + 0) * 64 + off] = h0;
    Hout[(size_t)(s0 + 1) * 64 + off] = h1;
    Hout[(size_t)(s0 + 2) * 64 + off] = h2;
    Hout[(size_t)(s0 + 3) * 64 + off] = h3;
}

// ============================================================================
// Ragged segment mean/min/max over g_h2. One block (64 threads) per batch row.
// ============================================================================
__global__ void seg_kernel(const int* __restrict__ elems)
{
    const int b   = blockIdx.x;
    const int tid = threadIdx.x;   // 0..63
    __shared__ int sred[64];

    int partial = 0;
    for (int i = tid; i < b; i += 64) partial += elems[i];
    sred[tid] = partial;
    __syncthreads();
    for (int s = 32; s; s >>= 1) {
        if (tid < s) sred[tid] += sred[tid + s];
        __syncthreads();
    }
    const int off = sred[0];
    const int cnt = elems[b];

    float s = 0.f, mn = 3.402823466e38f, mx = -3.402823466e38f;
    const float* base = g_h2 + (size_t)off * 64 + tid;
    int r = 0;
    for (; r + 4 <= cnt; r += 4) {
        float v0 = base[(size_t)(r + 0) * 64];
        float v1 = base[(size_t)(r + 1) * 64];
        float v2 = base[(size_t)(r + 2) * 64];
        float v3 = base[(size_t)(r + 3) * 64];
        s += (v0 + v1) + (v2 + v3);
        mn = fminf(mn, fminf(fminf(v0, v1), fminf(v2, v3)));
        mx = fmaxf(mx, fmaxf(fmaxf(v0, v1), fmaxf(v2, v3)));
    }
    for (; r < cnt; ++r) {
        float v = base[(size_t)r * 64];
        s += v; mn = fminf(mn, v); mx = fmaxf(mx, v);
    }
    g_mean[b * 64 + tid] = s / (float)cnt;
    g_min[b * 64 + tid]  = mn;
    g_max[b * 64 + tid]  = mx;
}

// ============================================================================
// Head: concat(305) -> fc1 tanh -> fc2 sigmoid. 128 threads per batch row.
// ============================================================================
__global__ void __launch_bounds__(128) head_kernel(
    const float* __restrict__ normal,
    const float* __restrict__ fc1w, const float* __restrict__ fc1b,
    const float* __restrict__ fc2w, const float* __restrict__ fc2b,
    float* __restrict__ out)
{
    const int b    = blockIdx.x;
    const int tid  = threadIdx.x;
    const int wq   = tid >> 5;
    const int lane = tid & 31;
    __shared__ float xr[FC_IN + 3];
    __shared__ float part[4][32];

    if (tid < 64) {
        xr[tid]       = g_hn[b * 64 + tid];
        xr[113 + tid] = g_mean[b * 64 + tid];
        xr[177 + tid] = g_min[b * 64 + tid];
        xr[241 + tid] = g_max[b * 64 + tid];
    }
    for (int i = tid; i < DNORM; i += 128) xr[64 + i] = normal[b * DNORM + i];
    __syncthreads();

    const int k0 = wq * 76;
    const int k1 = (wq == 3) ? FC_IN : k0 + 76;
    const float* wrow = fc1w + lane * FC_IN;
    float a0 = 0.f, a1 = 0.f, a2 = 0.f, a3 = 0.f;
    int k = k0;
    for (; k + 4 <= k1; k += 4) {
        a0 += xr[k]     * wrow[k];
        a1 += xr[k + 1] * wrow[k + 1];
        a2 += xr[k + 2] * wrow[k + 2];
        a3 += xr[k + 3] * wrow[k + 3];
    }
    for (; k < k1; ++k) a0 += xr[k] * wrow[k];
    part[wq][lane] = (a0 + a1) + (a2 + a3);
    __syncthreads();

    if (wq == 0) {
        float acc = fc1b[lane] + part[0][lane] + part[1][lane] + part[2][lane] + part[3][lane];
        float pv = fast_tanh(acc) * fc2w[lane];
#pragma unroll
        for (int o = 16; o; o >>= 1) pv += __shfl_xor_sync(0xffffffffu, pv, o);
        if (lane == 0) out[b] = fast_sigmoid(pv + fc2b[0]);
    }
}

// ============================================================================
// kernel_launch
// ============================================================================
extern "C" void kernel_launch(void* const* d_in, const int* in_sizes, int n_in,
                              void* d_out, int out_size)
{
    const float* normal   = (const float*)d_in[0];
    const float* text     = (const float*)d_in[1];
    const float* timeline = (const float*)d_in[2];

    const int* elems;
    int base;
    if (in_sizes[3] == BATCH) { elems = (const int*)d_in[3]; base = 4; }
    else                      { elems = (const int*)d_in[n_in - 1]; base = 3; }

    const float* r1[8];
    const float* r2[8];
    for (int i = 0; i < 8; ++i) r1[i] = (const float*)d_in[base + i];
    for (int i = 0; i < 8; ++i) r2[i] = (const float*)d_in[base + 8 + i];
    const float* fc1w = (const float*)d_in[base + 16];
    const float* fc1b = (const float*)d_in[base + 17];
    const float* fc2w = (const float*)d_in[base + 18];
    const float* fc2b = (const float*)d_in[base + 19];
    // per dir: wi, wh, bi, bh ; fwd then bwd

    float* hn; cudaGetSymbolAddress((void**)&hn, g_hn);
    float* h2; cudaGetSymbolAddress((void**)&h2, g_h2);

    // fused biRNN: warp = (4 seqs, 1 dir), 8 warps/block
    const int tlB = (NTL / 4 * 2) / 8;     // 2048 blocks
    const int txB = (BATCH / 4 * 2) / 8;   // 32 blocks
    fused_rnn_kernel<<<tlB + txB, 256>>>(
        tlB,
        timeline, h2, TTL,
        r2[0], r2[1], r2[2], r2[3], r2[4], r2[5], r2[6], r2[7],
        text, hn, TTEXT,
        r1[0], r1[1], r1[2], r1[3], r1[4], r1[5], r1[6], r1[7]);

    seg_kernel<<<BATCH, 64>>>(elems);

    head_kernel<<<BATCH, 128>>>(normal, fc1w, fc1b, fc2w, fc2b, (float*)d_out);
}

// round 5
// speedup vs baseline: 1.5602x; 1.0095x over previous
#include <cuda_runtime.h>
#include <cuda_bf16.h>
#include <math.h>
#include <stdint.h>

// Problem constants (fixed by setup_inputs)
#define BATCH   512
#define TTEXT   64
#define EDIM    50
#define HDIM    32
#define NTL     32768
#define TTL     32
#define DNORM   49
#define FC_IN   305   // 64 + 49 + 64 + 64 + 64

typedef unsigned long long u64t;

// -------- device scratch (static; no runtime allocation) --------
__device__ float g_hn[BATCH * 64];            // text biRNN final hidden [B, 2H]
__device__ float g_h2[NTL * 64];              // timeline biRNN final hidden [N, 2H]
__device__ float g_mean[BATCH * 64];
__device__ float g_min[BATCH * 64];
__device__ float g_max[BATCH * 64];

// ---------------- packed f32x2 helpers ----------------
__device__ __forceinline__ u64t pk2(float a, float b) {
    u64t r; asm("mov.b64 %0,{%1,%2};" : "=l"(r) : "f"(a), "f"(b)); return r;
}
__device__ __forceinline__ void upk2(u64t v, float& a, float& b) {
    asm("mov.b64 {%0,%1},%2;" : "=f"(a), "=f"(b) : "l"(v));
}
__device__ __forceinline__ u64t fma2(u64t a, u64t b, u64t c) {
    u64t d; asm("fma.rn.f32x2 %0,%1,%2,%3;" : "=l"(d) : "l"(a), "l"(b), "l"(c)); return d;
}
__device__ __forceinline__ u64t add2(u64t a, u64t b) {
    u64t d; asm("add.rn.f32x2 %0,%1,%2;" : "=l"(d) : "l"(a), "l"(b)); return d;
}

// tanh(x) = 1 - 2/(e^{2x}+1) via MUFU ex2/rcp.
__device__ __forceinline__ float fast_tanh(float x) {
    float e, r;
    asm("ex2.approx.f32 %0,%1;" : "=f"(e) : "f"(x * 2.8853900817779268f));
    asm("rcp.approx.f32 %0,%1;" : "=f"(r) : "f"(e + 1.0f));
    return fmaf(-2.0f, r, 1.0f);
}
__device__ __forceinline__ float fast_sigmoid(float x) {
    float e, r;
    asm("ex2.approx.f32 %0,%1;" : "=f"(e) : "f"(-x * 1.4426950408889634f));
    asm("rcp.approx.f32 %0,%1;" : "=f"(r) : "f"(e + 1.0f));
    return r;
}

// u-dot: 26 padded E-pairs (13 LDS.128), wi[25] must be {0,0}
__device__ __forceinline__ float u_dot(const u64t* __restrict__ xrow,
                                       const u64t* __restrict__ wi)
{
    const ulonglong2* x2 = (const ulonglong2*)xrow;
    u64t c0 = 0ull, c1 = 0ull;
#pragma unroll
    for (int jp = 0; jp < 13; ++jp) {
        ulonglong2 xx = x2[jp];            // LDS.128 broadcast
        c0 = fma2(xx.x, wi[2 * jp],     c0);
        c1 = fma2(xx.y, wi[2 * jp + 1], c1);
    }
    c0 = add2(c0, c1);
    float f0, f1; upk2(c0, f0, f1);
    return f0 + f1;
}

// ============================================================================
// Fused biRNN: h_t = tanh(x_t·Wih^T + bias + h_{t-1}·Whh^T), final h only.
// One warp = (8 sequences, 1 direction); lane = hidden unit.
// Wih (26 padded pairs) + Whh (16 natural pairs) in registers.
// Per-warp smem: double-buffered x tiles (8 x 26 u64, LDS.128 broadcast) and
// h rows (8 x 32 f32). Pipeline: LDG x_{t+2} | u_{t+1} | rec t | STS | sync.
// Merged launch: blocks [0, tlBlocks) -> timeline, rest -> text.
// ============================================================================
__global__ void __launch_bounds__(128, 3) fused_rnn_kernel(
    int tlBlocks,
    const float* __restrict__ Xl, float* __restrict__ Hl, int Tl,
    const float* __restrict__ l_Wif, const float* __restrict__ l_Whf,
    const float* __restrict__ l_bif, const float* __restrict__ l_bhf,
    const float* __restrict__ l_Wib, const float* __restrict__ l_Whb,
    const float* __restrict__ l_bib, const float* __restrict__ l_bhb,
    const float* __restrict__ Xt, float* __restrict__ Ht, int Tt,
    const float* __restrict__ t_Wif, const float* __restrict__ t_Whf,
    const float* __restrict__ t_bif, const float* __restrict__ t_bhf,
    const float* __restrict__ t_Wib, const float* __restrict__ t_Whb,
    const float* __restrict__ t_bib, const float* __restrict__ t_bhb)
{
    __shared__ __align__(16) u64t  sX[4][2][8][26];    // 13312 B
    __shared__ __align__(16) float sHf[4][2][8][HDIM]; // 8192 B

    const int tid  = threadIdx.x;
    const int w    = tid >> 5;
    const int lane = tid & 31;

    const bool isTL = (blockIdx.x < tlBlocks);
    const int  blk  = isTL ? blockIdx.x : (blockIdx.x - tlBlocks);
    const float* X  = isTL ? Xl : Xt;
    float*    Hout  = isTL ? Hl : Ht;
    const int T     = isTL ? Tl : Tt;

    const int gw = blk * 4 + w;
    const int g  = gw >> 1;          // group of 8 sequences
    const int d  = gw & 1;           // direction

    const float* Wi = isTL ? (d ? l_Wib : l_Wif) : (d ? t_Wib : t_Wif);
    const float* Wh = isTL ? (d ? l_Whb : l_Whf) : (d ? t_Whb : t_Whf);
    const float* bi = isTL ? (d ? l_bib : l_bif) : (d ? t_bib : t_bif);
    const float* bh = isTL ? (d ? l_bhb : l_bhf) : (d ? t_bhb : t_bhf);

    // per-lane weight rows -> registers
    u64t wi[26];
    {
        const u64t* Wi2 = (const u64t*)(Wi + lane * EDIM);
#pragma unroll
        for (int j = 0; j < 25; ++j) wi[j] = Wi2[j];
        wi[25] = 0ull;
    }
    u64t wh[16];   // natural pairs {Wh[l][2jp], Wh[l][2jp+1]}
    {
        const u64t* Wh2 = (const u64t*)(Wh + lane * HDIM);
#pragma unroll
        for (int jp = 0; jp < 16; ++jp) wh[jp] = Wh2[jp];
    }
    const float bias = bi[lane] + bh[lane];

    const int  s0  = 8 * g;
    const long sgn = d ? -25 : 25;                 // per-step stride in u64
    const long t0  = d ? (long)(T - 1) * 25 : 0;

    // staging map: flat slot = lane + 32k (k<7) covers 8x26 tile; j<25 real
    int  pfoff[7], stsoff[7];
    bool act[7];
#pragma unroll
    for (int k = 0; k < 7; ++k) {
        int flat = lane + 32 * k;
        int row = flat / 26, j = flat % 26;
        act[k] = (flat < 208) && (j < 25);
        if (!act[k]) { row = 0; j = 0; }
        pfoff[k]  = (int)((long)(s0 + row) * T * 25 + j);
        stsoff[k] = row * 26 + j;
    }

    u64t* sXw = &sX[w][0][0][0];                   // [buf*208 + row*26 + j]
    const u64t* XB = (const u64t*)X;

    // zero pad slots (j==25) in both buffers
    if (lane < 8) { sXw[lane * 26 + 25] = 0ull; sXw[208 + lane * 26 + 25] = 0ull; }

    // prologue: x0 -> buf0, x1 -> buf1
    {
        const u64t* Xp0 = XB + t0;
#pragma unroll
        for (int k = 0; k < 7; ++k)
            if (act[k]) sXw[stsoff[k]] = Xp0[pfoff[k]];
        if (T > 1) {
            const u64t* Xp1 = Xp0 + sgn;
#pragma unroll
            for (int k = 0; k < 7; ++k)
                if (act[k]) sXw[208 + stsoff[k]] = Xp1[pfoff[k]];
        }
    }
    // zero h_{-1}
#pragma unroll
    for (int s = 0; s < 8; ++s) sHf[w][0][s][lane] = 0.f;
    __syncwarp();

    // u for step 0
    float uc[8];
#pragma unroll
    for (int s = 0; s < 8; ++s) uc[s] = u_dot(sXw + s * 26, wi) + bias;

    const u64t* pfT = XB + t0 + 2 * sgn;           // source of x_{t+2}
    float hl[8];
#pragma unroll
    for (int s = 0; s < 8; ++s) hl[s] = 0.f;

    for (int t = 0; t < T; ++t) {
        const int cur = t & 1, nxt = cur ^ 1;

        // 1. prefetch x_{t+2} into registers
        u64t r[7];
        const bool havePF = (t + 2 < T);
        if (havePF) {
#pragma unroll
            for (int k = 0; k < 7; ++k)
                if (act[k]) r[k] = pfT[pfoff[k]];
        }
        pfT += sgn;

        // 2. compute u_{t+1} from buf[nxt]
        float un[8];
        if (t + 1 < T) {
            const u64t* xb = sXw + nxt * 208;
#pragma unroll
            for (int s = 0; s < 8; ++s) un[s] = u_dot(xb + s * 26, wi) + bias;
        } else {
#pragma unroll
            for (int s = 0; s < 8; ++s) un[s] = 0.f;
        }

        // 3. recurrence for step t (h_{t-1} in sHf[w][cur])
#pragma unroll
        for (int s = 0; s < 8; ++s) {
            const ulonglong2* h4 = (const ulonglong2*)&sHf[w][cur][s][0];
            u64t c0 = 0ull, c1 = 0ull;
#pragma unroll
            for (int i = 0; i < 8; ++i) {
                ulonglong2 hh = h4[i];             // LDS.128: h[4i..4i+3]
                c0 = fma2(hh.x, wh[2 * i],     c0);
                c1 = fma2(hh.y, wh[2 * i + 1], c1);
            }
            c0 = add2(c0, c1);
            float f0, f1; upk2(c0, f0, f1);
            hl[s] = fast_tanh(uc[s] + f0 + f1);
        }
#pragma unroll
        for (int s = 0; s < 8; ++s) sHf[w][nxt][s][lane] = hl[s];

        // 4. store x_{t+2} into buf[cur] (its x_t is dead)
        if (havePF) {
            u64t* xb = sXw + cur * 208;
#pragma unroll
            for (int k = 0; k < 7; ++k)
                if (act[k]) xb[stsoff[k]] = r[k];
        }
        __syncwarp();
#pragma unroll
        for (int s = 0; s < 8; ++s) uc[s] = un[s];
    }

    const int off = d * 32 + lane;
#pragma unroll
    for (int s = 0; s < 8; ++s)
        Hout[(size_t)(s0 + s) * 64 + off] = hl[s];
}

// ============================================================================
// Ragged segment mean/min/max over g_h2. One block (64 threads) per batch row.
// ============================================================================
__global__ void seg_kernel(const int* __restrict__ elems)
{
    const int b   = blockIdx.x;
    const int tid = threadIdx.x;   // 0..63
    __shared__ int sred[64];

    int partial = 0;
    for (int i = tid; i < b; i += 64) partial += elems[i];
    sred[tid] = partial;
    __syncthreads();
    for (int s = 32; s; s >>= 1) {
        if (tid < s) sred[tid] += sred[tid + s];
        __syncthreads();
    }
    const int off = sred[0];
    const int cnt = elems[b];

    float s = 0.f, mn = 3.402823466e38f, mx = -3.402823466e38f;
    const float* base = g_h2 + (size_t)off * 64 + tid;
    int r = 0;
    for (; r + 4 <= cnt; r += 4) {
        float v0 = base[(size_t)(r + 0) * 64];
        float v1 = base[(size_t)(r + 1) * 64];
        float v2 = base[(size_t)(r + 2) * 64];
        float v3 = base[(size_t)(r + 3) * 64];
        s += (v0 + v1) + (v2 + v3);
        mn = fminf(mn, fminf(fminf(v0, v1), fminf(v2, v3)));
        mx = fmaxf(mx, fmaxf(fmaxf(v0, v1), fmaxf(v2, v3)));
    }
    for (; r < cnt; ++r) {
        float v = base[(size_t)r * 64];
        s += v; mn = fminf(mn, v); mx = fmaxf(mx, v);
    }
    g_mean[b * 64 + tid] = s / (float)cnt;
    g_min[b * 64 + tid]  = mn;
    g_max[b * 64 + tid]  = mx;
}

// ============================================================================
// Head: concat(305) -> fc1 tanh -> fc2 sigmoid. 128 threads per batch row.
// ============================================================================
__global__ void __launch_bounds__(128) head_kernel(
    const float* __restrict__ normal,
    const float* __restrict__ fc1w, const float* __restrict__ fc1b,
    const float* __restrict__ fc2w, const float* __restrict__ fc2b,
    float* __restrict__ out)
{
    const int b    = blockIdx.x;
    const int tid  = threadIdx.x;
    const int wq   = tid >> 5;
    const int lane = tid & 31;
    __shared__ float xr[FC_IN + 3];
    __shared__ float part[4][32];

    if (tid < 64) {
        xr[tid]       = g_hn[b * 64 + tid];
        xr[113 + tid] = g_mean[b * 64 + tid];
        xr[177 + tid] = g_min[b * 64 + tid];
        xr[241 + tid] = g_max[b * 64 + tid];
    }
    for (int i = tid; i < DNORM; i += 128) xr[64 + i] = normal[b * DNORM + i];
    __syncthreads();

    const int k0 = wq * 76;
    const int k1 = (wq == 3) ? FC_IN : k0 + 76;
    const float* wrow = fc1w + lane * FC_IN;
    float a0 = 0.f, a1 = 0.f, a2 = 0.f, a3 = 0.f;
    int k = k0;
    for (; k + 4 <= k1; k += 4) {
        a0 += xr[k]     * wrow[k];
        a1 += xr[k + 1] * wrow[k + 1];
        a2 += xr[k + 2] * wrow[k + 2];
        a3 += xr[k + 3] * wrow[k + 3];
    }
    for (; k < k1; ++k) a0 += xr[k] * wrow[k];
    part[wq][lane] = (a0 + a1) + (a2 + a3);
    __syncthreads();

    if (wq == 0) {
        float acc = fc1b[lane] + part[0][lane] + part[1][lane] + part[2][lane] + part[3][lane];
        float pv = fast_tanh(acc) * fc2w[lane];
#pragma unroll
        for (int o = 16; o; o >>= 1) pv += __shfl_xor_sync(0xffffffffu, pv, o);
        if (lane == 0) out[b] = fast_sigmoid(pv + fc2b[0]);
    }
}

// ============================================================================
// kernel_launch
// ============================================================================
extern "C" void kernel_launch(void* const* d_in, const int* in_sizes, int n_in,
                              void* d_out, int out_size)
{
    const float* normal   = (const float*)d_in[0];
    const float* text     = (const float*)d_in[1];
    const float* timeline = (const float*)d_in[2];

    const int* elems;
    int base;
    if (in_sizes[3] == BATCH) { elems = (const int*)d_in[3]; base = 4; }
    else                      { elems = (const int*)d_in[n_in - 1]; base = 3; }

    const float* r1[8];
    const float* r2[8];
    for (int i = 0; i < 8; ++i) r1[i] = (const float*)d_in[base + i];
    for (int i = 0; i < 8; ++i) r2[i] = (const float*)d_in[base + 8 + i];
    const float* fc1w = (const float*)d_in[base + 16];
    const float* fc1b = (const float*)d_in[base + 17];
    const float* fc2w = (const float*)d_in[base + 18];
    const float* fc2b = (const float*)d_in[base + 19];
    // per dir: wi, wh, bi, bh ; fwd then bwd

    float* hn; cudaGetSymbolAddress((void**)&hn, g_hn);
    float* h2; cudaGetSymbolAddress((void**)&h2, g_h2);

    // fused biRNN: warp = (8 seqs, 1 dir), 4 warps/block (128 thr)
    const int tlB = (NTL / 8 * 2) / 4;     // 2048 blocks
    const int txB = (BATCH / 8 * 2) / 4;   // 32 blocks
    fused_rnn_kernel<<<tlB + txB, 128>>>(
        tlB,
        timeline, h2, TTL,
        r2[0], r2[1], r2[2], r2[3], r2[4], r2[5], r2[6], r2[7],
        text, hn, TTEXT,
        r1[0], r1[1], r1[2], r1[3], r1[4], r1[5], r1[6], r1[7]);

    seg_kernel<<<BATCH, 64>>>(elems);

    head_kernel<<<BATCH, 128>>>(normal, fc1w, fc1b, fc2w, fc2b, (float*)d_out);
}

// round 7
// speedup vs baseline: 1.9086x; 1.2233x over previous
#include <cuda_runtime.h>
#include <cuda_bf16.h>
#include <math.h>
#include <stdint.h>

// Problem constants (fixed by setup_inputs)
#define BATCH   512
#define TTEXT   64
#define EDIM    50
#define HDIM    32
#define NTL     32768
#define TTL     32
#define DNORM   49
#define FC_IN   305   // 64 + 49 + 64 + 64 + 64

typedef unsigned long long u64t;

// -------- device scratch (static; no runtime allocation) --------
__device__ float g_hn[BATCH * 64];            // text biRNN final hidden [B, 2H]
__device__ float g_h2[NTL * 64];              // timeline biRNN final hidden [N, 2H]
__device__ float g_mean[BATCH * 64];
__device__ float g_min[BATCH * 64];
__device__ float g_max[BATCH * 64];

// ---------------- packed f32x2 helpers ----------------
__device__ __forceinline__ u64t pk2(float a, float b) {
    u64t r; asm("mov.b64 %0,{%1,%2};" : "=l"(r) : "f"(a), "f"(b)); return r;
}
__device__ __forceinline__ void upk2(u64t v, float& a, float& b) {
    asm("mov.b64 {%0,%1},%2;" : "=f"(a), "=f"(b) : "l"(v));
}
__device__ __forceinline__ u64t fma2(u64t a, u64t b, u64t c) {
    u64t d; asm("fma.rn.f32x2 %0,%1,%2,%3;" : "=l"(d) : "l"(a), "l"(b), "l"(c)); return d;
}
__device__ __forceinline__ u64t add2(u64t a, u64t b) {
    u64t d; asm("add.rn.f32x2 %0,%1,%2;" : "=l"(d) : "l"(a), "l"(b)); return d;
}

// tanh(x) = 1 - 2/(e^{2x}+1) via MUFU ex2/rcp.
__device__ __forceinline__ float fast_tanh(float x) {
    float e, r;
    asm("ex2.approx.f32 %0,%1;" : "=f"(e) : "f"(x * 2.8853900817779268f));
    asm("rcp.approx.f32 %0,%1;" : "=f"(r) : "f"(e + 1.0f));
    return fmaf(-2.0f, r, 1.0f);
}
__device__ __forceinline__ float fast_sigmoid(float x) {
    float e, r;
    asm("ex2.approx.f32 %0,%1;" : "=f"(e) : "f"(-x * 1.4426950408889634f));
    asm("rcp.approx.f32 %0,%1;" : "=f"(r) : "f"(e + 1.0f));
    return r;
}

// ---------------- cp.async helpers (8-byte) ----------------
#define CP_ASYNC8(dst32, srcptr) \
    asm volatile("cp.async.ca.shared.global [%0], [%1], 8;" :: "r"(dst32), "l"(srcptr))
#define CP_COMMIT() asm volatile("cp.async.commit_group;" ::: "memory")
#define CP_WAIT0()  asm volatile("cp.async.wait_group 0;" ::: "memory")

// u-dot: 26 padded E-pairs (13 LDS.128); wi[25] and pad slots must be zero.
__device__ __forceinline__ float u_dot(const u64t* __restrict__ xrow,
                                       const u64t* __restrict__ wi)
{
    const ulonglong2* x2 = (const ulonglong2*)xrow;
    u64t c0 = 0ull, c1 = 0ull;
#pragma unroll
    for (int jp = 0; jp < 13; ++jp) {
        ulonglong2 xx = x2[jp];            // LDS.128 broadcast
        c0 = fma2(xx.x, wi[2 * jp],     c0);
        c1 = fma2(xx.y, wi[2 * jp + 1], c1);
    }
    c0 = add2(c0, c1);
    float f0, f1; upk2(c0, f0, f1);
    return f0 + f1;
}

// ============================================================================
// Fused biRNN: h_t = tanh(x_t·Wih^T + bias + h_{t-1}·Whh^T), final h only.
// One warp = (8 sequences, 1 direction); lane = hidden unit.
// Wih (26 padded pairs) + Whh (16 natural pairs) in registers.
// x staged via cp.async into double-buffered smem tiles (8 rows x 28 u64,
// pitch 28 so 224 slots = 7*32 lane-slots exactly). h double-buffered in smem.
// Pipeline: cp.async x_{t+2} | u_{t+1} | rec t | STS h | wait+sync.
// Merged launch: blocks [0, tlBlocks) -> timeline, rest -> text.
// ============================================================================
__global__ void __launch_bounds__(128, 3) fused_rnn_kernel(
    int tlBlocks,
    const float* __restrict__ Xl, float* __restrict__ Hl, int Tl,
    const float* __restrict__ l_Wif, const float* __restrict__ l_Whf,
    const float* __restrict__ l_bif, const float* __restrict__ l_bhf,
    const float* __restrict__ l_Wib, const float* __restrict__ l_Whb,
    const float* __restrict__ l_bib, const float* __restrict__ l_bhb,
    const float* __restrict__ Xt, float* __restrict__ Ht, int Tt,
    const float* __restrict__ t_Wif, const float* __restrict__ t_Whf,
    const float* __restrict__ t_bif, const float* __restrict__ t_bhf,
    const float* __restrict__ t_Wib, const float* __restrict__ t_Whb,
    const float* __restrict__ t_bib, const float* __restrict__ t_bhb)
{
    __shared__ __align__(16) u64t  sX[4][2][224];      // 14336 B (pitch 28/row)
    __shared__ __align__(16) float sHf[4][2][8][HDIM]; // 8192 B

    const int tid  = threadIdx.x;
    const int w    = tid >> 5;
    const int lane = tid & 31;

    const bool isTL = (blockIdx.x < tlBlocks);
    const int  blk  = isTL ? blockIdx.x : (blockIdx.x - tlBlocks);
    const float* X  = isTL ? Xl : Xt;
    float*    Hout  = isTL ? Hl : Ht;
    const int T     = isTL ? Tl : Tt;

    const int gw = blk * 4 + w;
    const int g  = gw >> 1;          // group of 8 sequences
    const int d  = gw & 1;           // direction

    const float* Wi = isTL ? (d ? l_Wib : l_Wif) : (d ? t_Wib : t_Wif);
    const float* Wh = isTL ? (d ? l_Whb : l_Whf) : (d ? t_Whb : t_Whf);
    const float* bi = isTL ? (d ? l_bib : l_bif) : (d ? t_bib : t_bif);
    const float* bh = isTL ? (d ? l_bhb : l_bhf) : (d ? t_bhb : t_bhf);

    // per-lane weight rows -> registers
    u64t wi[26];
    {
        const u64t* Wi2 = (const u64t*)(Wi + lane * EDIM);
#pragma unroll
        for (int j = 0; j < 25; ++j) wi[j] = Wi2[j];
        wi[25] = 0ull;
    }
    u64t wh[16];   // natural pairs {Wh[l][2jp], Wh[l][2jp+1]}
    {
        const u64t* Wh2 = (const u64t*)(Wh + lane * HDIM);
#pragma unroll
        for (int jp = 0; jp < 16; ++jp) wh[jp] = Wh2[jp];
    }
    const float bias = bi[lane] + bh[lane];

    const int s0  = 8 * g;
    const int sgn = d ? -25 : 25;                  // per-step stride in u64
    const int t0  = d ? (T - 1) * 25 : 0;

    // staging map: lane-slot k covers flat = lane + 32k of the 8x28 tile
    int  dstoff[7];     // byte offset within one buffer
    int  srcoff[7];     // u64 offset from (X + t*25) base
    bool act[7];
#pragma unroll
    for (int k = 0; k < 7; ++k) {
        int flat = lane + 32 * k;
        int row = flat / 28, j = flat % 28;
        act[k] = (j < 25);
        dstoff[k] = (row * 28 + j) * 8;
        srcoff[k] = (s0 + row) * T * 25 + j;
    }

    u64t* sXw = &sX[w][0][0];                       // buf stride 224 u64 = 1792 B
    const uint32_t sxb = (uint32_t)__cvta_generic_to_shared(sXw);

    // zero pad slots (j in 25..27, 8 rows, both buffers)
    if (lane < 24) {
        int row = lane / 3, jj = 25 + lane % 3;
        sXw[row * 28 + jj]       = 0ull;
        sXw[224 + row * 28 + jj] = 0ull;
    }

    const u64t* XB = (const u64t*)X;
    const u64t* b0 = XB + t0;                       // x_0 base
    // prologue: x0 -> buf0, x1 -> buf1
#pragma unroll
    for (int k = 0; k < 7; ++k)
        if (act[k]) CP_ASYNC8(sxb + dstoff[k], b0 + srcoff[k]);
    CP_COMMIT();
    {
        const u64t* b1 = b0 + sgn;
#pragma unroll
        for (int k = 0; k < 7; ++k)
            if (act[k]) CP_ASYNC8(sxb + 1792 + dstoff[k], b1 + srcoff[k]);
        CP_COMMIT();
    }
#pragma unroll
    for (int s = 0; s < 8; ++s) sHf[w][0][s][lane] = 0.f;
    CP_WAIT0();
    __syncwarp();

    // u for step 0
    float uc[8];
#pragma unroll
    for (int s = 0; s < 8; ++s) uc[s] = u_dot(sXw + s * 28, wi) + bias;

    const u64t* pfT = b0 + 2 * sgn;                 // source base of x_{t+2}
    float hl[8];
#pragma unroll
    for (int s = 0; s < 8; ++s) hl[s] = 0.f;

    for (int t = 0; t < T; ++t) {
        const int cur = t & 1, nxt = cur ^ 1;

        // 1. async-copy x_{t+2} into buf[cur] (its x_t is dead)
        if (t + 2 < T) {
            const uint32_t db = sxb + cur * 1792;
#pragma unroll
            for (int k = 0; k < 7; ++k)
                if (act[k]) CP_ASYNC8(db + dstoff[k], pfT + srcoff[k]);
        }
        CP_COMMIT();
        pfT += sgn;

        // 2. compute u_{t+1} from buf[nxt] (independent of h -> fills bubbles)
        float un[8];
        if (t + 1 < T) {
            const u64t* xb = sXw + nxt * 224;
#pragma unroll
            for (int s = 0; s < 8; ++s) un[s] = u_dot(xb + s * 28, wi) + bias;
        } else {
#pragma unroll
            for (int s = 0; s < 8; ++s) un[s] = 0.f;
        }

        // 3. recurrence for step t (h_{t-1} in sHf[w][cur])
#pragma unroll
        for (int s = 0; s < 8; ++s) {
            const ulonglong2* h4 = (const ulonglong2*)&sHf[w][cur][s][0];
            u64t c0 = 0ull, c1 = 0ull;
#pragma unroll
            for (int i = 0; i < 8; ++i) {
                ulonglong2 hh = h4[i];             // LDS.128 broadcast
                c0 = fma2(hh.x, wh[2 * i],     c0);
                c1 = fma2(hh.y, wh[2 * i + 1], c1);
            }
            c0 = add2(c0, c1);
            float f0, f1; upk2(c0, f0, f1);
            hl[s] = fast_tanh(uc[s] + f0 + f1);
        }
#pragma unroll
        for (int s = 0; s < 8; ++s) sHf[w][nxt][s][lane] = hl[s];

        // 4. x_{t+2} must be resident before next iteration reads buf[cur]
        CP_WAIT0();
        __syncwarp();
#pragma unroll
        for (int s = 0; s < 8; ++s) uc[s] = un[s];
    }

    const int off = d * 32 + lane;
#pragma unroll
    for (int s = 0; s < 8; ++s)
        Hout[(size_t)(s0 + s) * 64 + off] = hl[s];
}

// ============================================================================
// Ragged segment mean/min/max over g_h2. One block (64 threads) per batch row.
// ============================================================================
__global__ void seg_kernel(const int* __restrict__ elems)
{
    const int b   = blockIdx.x;
    const int tid = threadIdx.x;   // 0..63
    __shared__ int sred[64];

    int partial = 0;
    for (int i = tid; i < b; i += 64) partial += elems[i];
    sred[tid] = partial;
    __syncthreads();
    for (int s = 32; s; s >>= 1) {
        if (tid < s) sred[tid] += sred[tid + s];
        __syncthreads();
    }
    const int off = sred[0];
    const int cnt = elems[b];

    float s = 0.f, mn = 3.402823466e38f, mx = -3.402823466e38f;
    const float* base = g_h2 + (size_t)off * 64 + tid;
    int r = 0;
    for (; r + 4 <= cnt; r += 4) {
        float v0 = base[(size_t)(r + 0) * 64];
        float v1 = base[(size_t)(r + 1) * 64];
        float v2 = base[(size_t)(r + 2) * 64];
        float v3 = base[(size_t)(r + 3) * 64];
        s += (v0 + v1) + (v2 + v3);
        mn = fminf(mn, fminf(fminf(v0, v1), fminf(v2, v3)));
        mx = fmaxf(mx, fmaxf(fmaxf(v0, v1), fmaxf(v2, v3)));
    }
    for (; r < cnt; ++r) {
        float v = base[(size_t)r * 64];
        s += v; mn = fminf(mn, v); mx = fmaxf(mx, v);
    }
    g_mean[b * 64 + tid] = s / (float)cnt;
    g_min[b * 64 + tid]  = mn;
    g_max[b * 64 + tid]  = mx;
}

// ============================================================================
// Head: concat(305) -> fc1 tanh -> fc2 sigmoid. 128 threads per batch row.
// ============================================================================
__global__ void __launch_bounds__(128) head_kernel(
    const float* __restrict__ normal,
    const float* __restrict__ fc1w, const float* __restrict__ fc1b,
    const float* __restrict__ fc2w, const float* __restrict__ fc2b,
    float* __restrict__ out)
{
    const int b    = blockIdx.x;
    const int tid  = threadIdx.x;
    const int wq   = tid >> 5;
    const int lane = tid & 31;
    __shared__ float xr[FC_IN + 3];
    __shared__ float part[4][32];

    if (tid < 64) {
        xr[tid]       = g_hn[b * 64 + tid];
        xr[113 + tid] = g_mean[b * 64 + tid];
        xr[177 + tid] = g_min[b * 64 + tid];
        xr[241 + tid] = g_max[b * 64 + tid];
    }
    for (int i = tid; i < DNORM; i += 128) xr[64 + i] = normal[b * DNORM + i];
    __syncthreads();

    const int k0 = wq * 76;
    const int k1 = (wq == 3) ? FC_IN : k0 + 76;
    const float* wrow = fc1w + lane * FC_IN;
    float a0 = 0.f, a1 = 0.f, a2 = 0.f, a3 = 0.f;
    int k = k0;
    for (; k + 4 <= k1; k += 4) {
        a0 += xr[k]     * wrow[k];
        a1 += xr[k + 1] * wrow[k + 1];
        a2 += xr[k + 2] * wrow[k + 2];
        a3 += xr[k + 3] * wrow[k + 3];
    }
    for (; k < k1; ++k) a0 += xr[k] * wrow[k];
    part[wq][lane] = (a0 + a1) + (a2 + a3);
    __syncthreads();

    if (wq == 0) {
        float acc = fc1b[lane] + part[0][lane] + part[1][lane] + part[2][lane] + part[3][lane];
        float pv = fast_tanh(acc) * fc2w[lane];
#pragma unroll
        for (int o = 16; o; o >>= 1) pv += __shfl_xor_sync(0xffffffffu, pv, o);
        if (lane == 0) out[b] = fast_sigmoid(pv + fc2b[0]);
    }
}

// ============================================================================
// kernel_launch
// ============================================================================
extern "C" void kernel_launch(void* const* d_in, const int* in_sizes, int n_in,
                              void* d_out, int out_size)
{
    const float* normal   = (const float*)d_in[0];
    const float* text     = (const float*)d_in[1];
    const float* timeline = (const float*)d_in[2];

    const int* elems;
    int base;
    if (in_sizes[3] == BATCH) { elems = (const int*)d_in[3]; base = 4; }
    else                      { elems = (const int*)d_in[n_in - 1]; base = 3; }

    const float* r1[8];
    const float* r2[8];
    for (int i = 0; i < 8; ++i) r1[i] = (const float*)d_in[base + i];
    for (int i = 0; i < 8; ++i) r2[i] = (const float*)d_in[base + 8 + i];
    const float* fc1w = (const float*)d_in[base + 16];
    const float* fc1b = (const float*)d_in[base + 17];
    const float* fc2w = (const float*)d_in[base + 18];
    const float* fc2b = (const float*)d_in[base + 19];
    // per dir: wi, wh, bi, bh ; fwd then bwd

    float* hn; cudaGetSymbolAddress((void**)&hn, g_hn);
    float* h2; cudaGetSymbolAddress((void**)&h2, g_h2);

    // fused biRNN: warp = (8 seqs, 1 dir), 4 warps/block (128 thr)
    const int tlB = (NTL / 8 * 2) / 4;     // 2048 blocks
    const int txB = (BATCH / 8 * 2) / 4;   // 32 blocks
    fused_rnn_kernel<<<tlB + txB, 128>>>(
        tlB,
        timeline, h2, TTL,
        r2[0], r2[1], r2[2], r2[3], r2[4], r2[5], r2[6], r2[7],
        text, hn, TTEXT,
        r1[0], r1[1], r1[2], r1[3], r1[4], r1[5], r1[6], r1[7]);

    seg_kernel<<<BATCH, 64>>>(elems);

    head_kernel<<<BATCH, 128>>>(normal, fc1w, fc1b, fc2w, fc2b, (float*)d_out);
}